// round 7
// baseline (speedup 1.0000x reference)
#include <cuda_runtime.h>
#include <math.h>

#define B_    8
#define C_    128
#define H_    224
#define W_    224
#define KTAP  7
#define RAD   6
#define TILE_H 32
#define SROWS (TILE_H + 2*RAD)      // 44
#define WF4   (W_/4)                // 56
#define SSTRIDE 60                  // float4 per smem row: 2 halo + 56 + 2 halo
#define NTHREADS 224

typedef unsigned long long u64;

__device__ __forceinline__ u64 pack2(float lo, float hi) {
    u64 r;
    asm("mov.b64 %0, {%1, %2};" : "=l"(r) : "f"(lo), "f"(hi));
    return r;
}
__device__ __forceinline__ void unpack2(u64 v, float& lo, float& hi) {
    asm("mov.b64 {%0, %1}, %2;" : "=f"(lo), "=f"(hi) : "l"(v));
}
// d = a*b + c on packed f32x2 (one issue slot for 2 FMAs)
__device__ __forceinline__ u64 fma2(u64 a, u64 b, u64 c) {
    u64 d;
    asm("fma.rn.f32x2 %0, %1, %2, %3;" : "=l"(d) : "l"(a), "l"(b), "l"(c));
    return d;
}

// ---------------------------------------------------------------------------
// Fast path (valid for 1 <= r < 2 : effective taps fit in radius 6).
// out = conv13_H(x) + conv13_W(x) with per-channel effective coefficients;
// identity (+x) folded into the H-filter center tap. All accumulation in
// fma.rn.f32x2 packed pairs.
// ---------------------------------------------------------------------------
__global__ __launch_bounds__(NTHREADS, 2)
void deform_axial_fast(const float* __restrict__ x,
                       const float* __restrict__ wh,
                       const float* __restrict__ ww,
                       const float* __restrict__ rp,
                       float* __restrict__ out)
{
    float rv = fmaxf(rp[0], 1.0f);
    if (!(rv < 2.0f)) return;   // uniform branch: generic kernel handles r >= 2

    __shared__ float4 s[SROWS * SSTRIDE];
    __shared__ float sch[13];
    __shared__ float scw[13];

    const int tid    = threadIdx.x;
    const int bc     = blockIdx.y;            // plane index in [0, B*C)
    const int ch     = bc % C_;               // channel
    const int hstart = blockIdx.x * TILE_H;

    const float4* xp = (const float4*)(x + (size_t)bc * (H_ * W_));
    float4*       op = (float4*)(out + (size_t)bc * (H_ * W_));

    // Build effective 13-tap filters (runtime r, per channel). One thread.
    if (tid == 0) {
        #pragma unroll
        for (int j = 0; j < 13; ++j) { sch[j] = 0.0f; scw[j] = 0.0f; }
        sch[RAD] = 1.0f;  // identity term
        #pragma unroll
        for (int k = 0; k < KTAP; ++k) {
            float delta = (float)(k - KTAP/2) * rv;
            float d0f   = floorf(delta);
            float fr    = delta - d0f;
            int   d0    = (int)d0f;           // in [-6, 5] since r < 2
            float a = wh[ch * KTAP + k];
            float b = ww[ch * KTAP + k];
            sch[d0 + 6] += (1.0f - fr) * a;
            sch[d0 + 7] += fr * a;
            scw[d0 + 6] += (1.0f - fr) * b;
            scw[d0 + 7] += fr * b;
        }
    }

    // Cooperative tile load: rows [hstart-6, hstart+TILE_H+6), full width.
    for (int idx = tid; idx < SROWS * WF4; idx += NTHREADS) {
        int row = idx / WF4, col = idx % WF4;
        int gh  = hstart - RAD + row;
        float4 v = make_float4(0.f, 0.f, 0.f, 0.f);
        if (gh >= 0 && gh < H_) v = xp[gh * WF4 + col];
        s[row * SSTRIDE + 2 + col] = v;
    }
    // Zero W halos (2 float4 each side per row)
    for (int idx = tid; idx < SROWS * 4; idx += NTHREADS) {
        int row = idx / 4, c4 = idx % 4;
        int col = (c4 < 2) ? c4 : (SSTRIDE - 4 + c4);
        s[row * SSTRIDE + col] = make_float4(0.f, 0.f, 0.f, 0.f);
    }
    __syncthreads();   // covers coeff build + tile load

    const int wq    = tid % WF4;   // float4 column 0..55
    const int ty    = tid / WF4;   // 0..3
    const int rbase = ty * 8;      // 8 output rows per thread

    // H-pass coefficients, broadcast-packed
    u64 chp[13];
    #pragma unroll
    for (int j = 0; j < 13; ++j) chp[j] = pack2(sch[j], sch[j]);

    u64 accl[8], acch[8];
    #pragma unroll
    for (int o = 0; o < 8; ++o) { accl[o] = 0ull; acch[o] = 0ull; }  // bits of (0f,0f)

    // H-pass: sliding window over 20 input rows feeds 8 outputs x 13 taps.
    #pragma unroll
    for (int jr = 0; jr < 20; ++jr) {
        float4 v = s[(rbase + jr) * SSTRIDE + 2 + wq];
        u64 vl = pack2(v.x, v.y);
        u64 vh = pack2(v.z, v.w);
        #pragma unroll
        for (int o = 0; o < 8; ++o) {
            int j = jr - o;
            if (j >= 0 && j < 13) {
                accl[o] = fma2(vl, chp[j], accl[o]);
                acch[o] = fma2(vh, chp[j], acch[o]);
            }
        }
    }

    // W-pass coefficients, broadcast-packed
    u64 cwp[13];
    #pragma unroll
    for (int j = 0; j < 13; ++j) cwp[j] = pack2(scw[j], scw[j]);

    // W-pass per row: 5 float4 loads cover the 20-float window.
    // f[i] = row float at global w-index 4*wq - 8 + i.
    // out.x (w=4wq) tap j: f[j+2]; y: f[j+3]; z: f[j+4]; w: f[j+5].
    // pk[i] = (f[2+i], f[3+i]) -> (x,y) uses pk[j], (z,w) uses pk[j+2].
    #pragma unroll
    for (int o = 0; o < 8; ++o) {
        const float4* r4 = &s[(rbase + o + RAD) * SSTRIDE];
        float f[20];
        #pragma unroll
        for (int m = 0; m < 5; ++m) {
            float4 v = r4[wq + m];
            f[4*m+0] = v.x; f[4*m+1] = v.y; f[4*m+2] = v.z; f[4*m+3] = v.w;
        }
        u64 pk[15];
        #pragma unroll
        for (int i = 0; i < 15; ++i) pk[i] = pack2(f[2 + i], f[3 + i]);

        u64 rl = accl[o], rh = acch[o];
        #pragma unroll
        for (int j = 0; j < 13; ++j) {
            rl = fma2(pk[j],     cwp[j], rl);
            rh = fma2(pk[j + 2], cwp[j], rh);
        }
        float4 res;
        unpack2(rl, res.x, res.y);
        unpack2(rh, res.z, res.w);
        // Streaming (evict-first) store: output never re-read; keep L2 for halos.
        __stcs(&op[(hstart + rbase + o) * WF4 + wq], res);
    }
}

// ---------------------------------------------------------------------------
// Generic fallback (any r >= 2). Grid-stride; exits instantly when r < 2.
// ---------------------------------------------------------------------------
__global__ void deform_axial_generic(const float* __restrict__ x,
                                     const float* __restrict__ wh,
                                     const float* __restrict__ ww,
                                     const float* __restrict__ rp,
                                     float* __restrict__ out,
                                     long total)
{
    float rv = fmaxf(rp[0], 1.0f);
    if (rv < 2.0f) return;

    long stride = (long)gridDim.x * blockDim.x;
    for (long i = (long)blockIdx.x * blockDim.x + threadIdx.x; i < total; i += stride) {
        int w  = (int)(i % W_);
        int h  = (int)((i / W_) % H_);
        long pl = i / (long)(H_ * W_);
        int c  = (int)(pl % C_);
        const float* plane = x + pl * (long)(H_ * W_);

        float res = plane[h * W_ + w];
        for (int k = 0; k < KTAP; ++k) {
            float delta = (float)(k - KTAP/2) * rv;
            float d0f   = floorf(delta);
            float fr    = delta - d0f;
            int   d0    = (int)d0f;

            int h0 = h + d0, h1 = h0 + 1;
            float s0 = (h0 >= 0 && h0 < H_) ? plane[h0 * W_ + w] : 0.f;
            float s1 = (h1 >= 0 && h1 < H_) ? plane[h1 * W_ + w] : 0.f;
            res += ((1.f - fr) * s0 + fr * s1) * wh[c * KTAP + k];

            int w0 = w + d0, w1 = w0 + 1;
            float t0 = (w0 >= 0 && w0 < W_) ? plane[h * W_ + w0] : 0.f;
            float t1 = (w1 >= 0 && w1 < W_) ? plane[h * W_ + w1] : 0.f;
            res += ((1.f - fr) * t0 + fr * t1) * ww[c * KTAP + k];
        }
        out[i] = res;
    }
}

extern "C" void kernel_launch(void* const* d_in, const int* in_sizes, int n_in,
                              void* d_out, int out_size)
{
    const float* x  = (const float*)d_in[0];
    const float* wh = (const float*)d_in[1];   // (C,1,7,1) -> C x 7 contiguous
    const float* ww = (const float*)d_in[2];   // (C,1,1,7) -> C x 7 contiguous
    const float* r  = (const float*)d_in[3];
    float* out = (float*)d_out;

    dim3 grid(H_ / TILE_H, B_ * C_);
    deform_axial_fast<<<grid, NTHREADS>>>(x, wh, ww, r, out);

    long total = (long)B_ * C_ * H_ * W_;
    deform_axial_generic<<<296, 256>>>(x, wh, ww, r, out, total);
}

// round 14
// speedup vs baseline: 1.5207x; 1.5207x over previous
#include <cuda_runtime.h>
#include <math.h>

#define B_    8
#define C_    128
#define H_    224
#define W_    224
#define KTAP  7
#define RAD   6
#define TILE_H 32
#define SROWS (TILE_H + 2*RAD)      // 44
#define WF4   (W_/4)                // 56
#define SSTRIDE 60                  // float4 per smem row: 2 halo + 56 + 2 halo
#define NTHREADS 224

typedef unsigned long long u64;

__device__ __forceinline__ u64 pack2(float lo, float hi) {
    u64 r;
    asm("mov.b64 %0, {%1, %2};" : "=l"(r) : "f"(lo), "f"(hi));
    return r;
}
__device__ __forceinline__ void unpack2(u64 v, float& lo, float& hi) {
    asm("mov.b64 {%0, %1}, %2;" : "=f"(lo), "=f"(hi) : "l"(v));
}
// d = a*b + c on packed f32x2 (one issue slot for 2 FMAs)
__device__ __forceinline__ u64 fma2(u64 a, u64 b, u64 c) {
    u64 d;
    asm("fma.rn.f32x2 %0, %1, %2, %3;" : "=l"(d) : "l"(a), "l"(b), "l"(c));
    return d;
}

// ---------------------------------------------------------------------------
// Single fused kernel.
//  r < 2  (always true for this problem's inputs): tiled 2x conv13 path.
//         out = conv13_H(x) + conv13_W(x), identity folded into H center tap.
//         H-pass in fma.rn.f32x2; W-pass scalar FFMA (register pressure).
//  r >= 2: per-element reference-style gather over this block's tile
//          (uniform branch; full output coverage, any r).
// ---------------------------------------------------------------------------
__global__ __launch_bounds__(NTHREADS, 3)
void deform_axial_kernel(const float* __restrict__ x,
                         const float* __restrict__ wh,
                         const float* __restrict__ ww,
                         const float* __restrict__ rp,
                         float* __restrict__ out)
{
    const float rv = fmaxf(rp[0], 1.0f);

    __shared__ float4 s[SROWS * SSTRIDE];
    __shared__ float sch[13];
    __shared__ float scw[13];

    const int tid    = threadIdx.x;
    const int bc     = blockIdx.y;            // plane index in [0, B*C)
    const int ch     = bc % C_;               // channel
    const int hstart = blockIdx.x * TILE_H;

    const int wq    = tid % WF4;   // float4 column 0..55
    const int ty    = tid / WF4;   // 0..3
    const int rbase = ty * 8;      // 8 output rows per thread

    if (rv < 2.0f) {
        // ---------------- fast tiled path ----------------
        const float4* xp = (const float4*)(x + (size_t)bc * (H_ * W_));
        float4*       op = (float4*)(out + (size_t)bc * (H_ * W_));

        // Build effective 13-tap filters (runtime r, per channel). One thread.
        if (tid == 0) {
            #pragma unroll
            for (int j = 0; j < 13; ++j) { sch[j] = 0.0f; scw[j] = 0.0f; }
            sch[RAD] = 1.0f;  // identity term
            #pragma unroll
            for (int k = 0; k < KTAP; ++k) {
                float delta = (float)(k - KTAP/2) * rv;
                float d0f   = floorf(delta);
                float fr    = delta - d0f;
                int   d0    = (int)d0f;       // in [-6, 5] since r < 2
                float a = wh[ch * KTAP + k];
                float b = ww[ch * KTAP + k];
                sch[d0 + 6] += (1.0f - fr) * a;
                sch[d0 + 7] += fr * a;
                scw[d0 + 6] += (1.0f - fr) * b;
                scw[d0 + 7] += fr * b;
            }
        }

        // Cooperative tile load: rows [hstart-6, hstart+TILE_H+6), full width.
        for (int idx = tid; idx < SROWS * WF4; idx += NTHREADS) {
            int row = idx / WF4, col = idx % WF4;
            int gh  = hstart - RAD + row;
            float4 v = make_float4(0.f, 0.f, 0.f, 0.f);
            if (gh >= 0 && gh < H_) v = xp[gh * WF4 + col];
            s[row * SSTRIDE + 2 + col] = v;
        }
        // Zero W halos (2 float4 each side per row)
        for (int idx = tid; idx < SROWS * 4; idx += NTHREADS) {
            int row = idx / 4, c4 = idx % 4;
            int col = (c4 < 2) ? c4 : (SSTRIDE - 4 + c4);
            s[row * SSTRIDE + col] = make_float4(0.f, 0.f, 0.f, 0.f);
        }
        __syncthreads();   // covers coeff build + tile load

        // H-pass coefficients, broadcast-packed for f32x2
        u64 chp[13];
        #pragma unroll
        for (int j = 0; j < 13; ++j) chp[j] = pack2(sch[j], sch[j]);

        u64 accl[8], acch[8];
        #pragma unroll
        for (int o = 0; o < 8; ++o) { accl[o] = 0ull; acch[o] = 0ull; }

        // H-pass: sliding window over 20 input rows -> 8 outputs x 13 taps.
        #pragma unroll
        for (int jr = 0; jr < 20; ++jr) {
            float4 v = s[(rbase + jr) * SSTRIDE + 2 + wq];
            u64 vl = pack2(v.x, v.y);
            u64 vh = pack2(v.z, v.w);
            #pragma unroll
            for (int o = 0; o < 8; ++o) {
                int j = jr - o;
                if (j >= 0 && j < 13) {
                    accl[o] = fma2(vl, chp[j], accl[o]);
                    acch[o] = fma2(vh, chp[j], acch[o]);
                }
            }
        }

        // W-pass coefficients, scalar (low register pressure)
        float cw[13];
        #pragma unroll
        for (int j = 0; j < 13; ++j) cw[j] = scw[j];

        // W-pass per row: 5 float4 loads cover the 20-float window.
        // f[i] = row float at global w-index 4*wq - 8 + i.
        // out.x (w=4wq) tap j: f[j+2]; y: f[j+3]; z: f[j+4]; w: f[j+5].
        #pragma unroll
        for (int o = 0; o < 8; ++o) {
            const float4* r4 = &s[(rbase + o + RAD) * SSTRIDE];
            float f[20];
            #pragma unroll
            for (int m = 0; m < 5; ++m) {
                float4 v = r4[wq + m];
                f[4*m+0] = v.x; f[4*m+1] = v.y; f[4*m+2] = v.z; f[4*m+3] = v.w;
            }
            float4 res;
            unpack2(accl[o], res.x, res.y);
            unpack2(acch[o], res.z, res.w);
            #pragma unroll
            for (int j = 0; j < 13; ++j) {
                float cc = cw[j];
                res.x = fmaf(cc, f[2 + j], res.x);
                res.y = fmaf(cc, f[3 + j], res.y);
                res.z = fmaf(cc, f[4 + j], res.z);
                res.w = fmaf(cc, f[5 + j], res.w);
            }
            // Streaming store: output never re-read; keep L2 for halos.
            __stcs(&op[(hstart + rbase + o) * WF4 + wq], res);
        }
    } else {
        // ---------------- generic path (r >= 2), per-element ----------------
        const float* plane = x + (size_t)bc * (H_ * W_);
        float*       oplane = out + (size_t)bc * (H_ * W_);
        for (int o = 0; o < 8; ++o) {
            int h = hstart + rbase + o;
            for (int c4 = 0; c4 < 4; ++c4) {
                int w = 4 * wq + c4;
                float res = plane[h * W_ + w];
                for (int k = 0; k < KTAP; ++k) {
                    float delta = (float)(k - KTAP/2) * rv;
                    float d0f   = floorf(delta);
                    float fr    = delta - d0f;
                    int   d0    = (int)d0f;

                    int h0 = h + d0, h1 = h0 + 1;
                    float s0 = (h0 >= 0 && h0 < H_) ? plane[h0 * W_ + w] : 0.f;
                    float s1 = (h1 >= 0 && h1 < H_) ? plane[h1 * W_ + w] : 0.f;
                    res += ((1.f - fr) * s0 + fr * s1) * wh[ch * KTAP + k];

                    int w0 = w + d0, w1 = w0 + 1;
                    float t0 = (w0 >= 0 && w0 < W_) ? plane[h * W_ + w0] : 0.f;
                    float t1 = (w1 >= 0 && w1 < W_) ? plane[h * W_ + w1] : 0.f;
                    res += ((1.f - fr) * t0 + fr * t1) * ww[ch * KTAP + k];
                }
                oplane[h * W_ + w] = res;
            }
        }
    }
}

extern "C" void kernel_launch(void* const* d_in, const int* in_sizes, int n_in,
                              void* d_out, int out_size)
{
    const float* x  = (const float*)d_in[0];
    const float* wh = (const float*)d_in[1];   // (C,1,7,1) -> C x 7 contiguous
    const float* ww = (const float*)d_in[2];   // (C,1,1,7) -> C x 7 contiguous
    const float* r  = (const float*)d_in[3];
    float* out = (float*)d_out;

    dim3 grid(H_ / TILE_H, B_ * C_);
    deform_axial_kernel<<<grid, NTHREADS>>>(x, wh, ww, r, out);
}

// round 17
// speedup vs baseline: 2.2811x; 1.5000x over previous
#include <cuda_runtime.h>
#include <math.h>

#define B_    8
#define C_    128
#define H_    224
#define W_    224
#define KTAP  7
#define RAD   6
#define TILE_H 16
#define ROWS_PT 4                   // output rows per thread
#define SROWS (TILE_H + 2*RAD)      // 28
#define WF4   (W_/4)                // 56
#define SSTRIDE 60                  // float4 per smem row: 2 halo + 56 + 2 halo
#define NTHREADS 224

typedef unsigned long long u64;

__device__ __forceinline__ u64 pack2(float lo, float hi) {
    u64 r;
    asm("mov.b64 %0, {%1, %2};" : "=l"(r) : "f"(lo), "f"(hi));
    return r;
}
__device__ __forceinline__ void unpack2(u64 v, float& lo, float& hi) {
    asm("mov.b64 {%0, %1}, %2;" : "=f"(lo), "=f"(hi) : "l"(v));
}
// d = a*b + c on packed f32x2 (one issue slot for 2 FMAs)
__device__ __forceinline__ u64 fma2(u64 a, u64 b, u64 c) {
    u64 d;
    asm("fma.rn.f32x2 %0, %1, %2, %3;" : "=l"(d) : "l"(a), "l"(b), "l"(c));
    return d;
}

// ---------------------------------------------------------------------------
// Single fused kernel, occupancy-4 configuration (latency-bound fix).
//  r < 2: tiled conv13_H + conv13_W path, identity folded into H center tap.
//         TILE_H=16, 4 rows/thread -> small live set, 28 warps/SM.
//  r >= 2: per-element reference-style gather (uniform branch, full coverage).
// ---------------------------------------------------------------------------
__global__ __launch_bounds__(NTHREADS, 4)
void deform_axial_kernel(const float* __restrict__ x,
                         const float* __restrict__ wh,
                         const float* __restrict__ ww,
                         const float* __restrict__ rp,
                         float* __restrict__ out)
{
    const float rv = fmaxf(rp[0], 1.0f);

    __shared__ float4 s[SROWS * SSTRIDE];
    __shared__ float sch[13];
    __shared__ float scw[13];

    const int tid    = threadIdx.x;
    const int bc     = blockIdx.y;            // plane index in [0, B*C)
    const int ch     = bc % C_;               // channel
    const int hstart = blockIdx.x * TILE_H;

    const int wq    = tid % WF4;   // float4 column 0..55
    const int ty    = tid / WF4;   // 0..3
    const int rbase = ty * ROWS_PT; // 4 output rows per thread

    if (rv < 2.0f) {
        // ---------------- fast tiled path ----------------
        const float4* xp = (const float4*)(x + (size_t)bc * (H_ * W_));
        float4*       op = (float4*)(out + (size_t)bc * (H_ * W_));

        // Build effective 13-tap filters (runtime r, per channel). One thread.
        if (tid == 0) {
            #pragma unroll
            for (int j = 0; j < 13; ++j) { sch[j] = 0.0f; scw[j] = 0.0f; }
            sch[RAD] = 1.0f;  // identity term
            #pragma unroll
            for (int k = 0; k < KTAP; ++k) {
                float delta = (float)(k - KTAP/2) * rv;
                float d0f   = floorf(delta);
                float fr    = delta - d0f;
                int   d0    = (int)d0f;       // in [-6, 5] since r < 2
                float a = wh[ch * KTAP + k];
                float b = ww[ch * KTAP + k];
                sch[d0 + 6] += (1.0f - fr) * a;
                sch[d0 + 7] += fr * a;
                scw[d0 + 6] += (1.0f - fr) * b;
                scw[d0 + 7] += fr * b;
            }
        }

        // Cooperative tile load: rows [hstart-6, hstart+TILE_H+6), full width.
        // SROWS*WF4 = 1568 = 7 iterations of 224 -> unrolled for LDG MLP.
        #pragma unroll
        for (int it = 0; it < (SROWS * WF4 + NTHREADS - 1) / NTHREADS; ++it) {
            int idx = it * NTHREADS + tid;
            if (idx < SROWS * WF4) {
                int row = idx / WF4, col = idx % WF4;
                int gh  = hstart - RAD + row;
                float4 v = make_float4(0.f, 0.f, 0.f, 0.f);
                if (gh >= 0 && gh < H_) v = xp[gh * WF4 + col];
                s[row * SSTRIDE + 2 + col] = v;
            }
        }
        // Zero W halos (2 float4 each side per row)
        for (int idx = tid; idx < SROWS * 4; idx += NTHREADS) {
            int row = idx / 4, c4 = idx % 4;
            int col = (c4 < 2) ? c4 : (SSTRIDE - 4 + c4);
            s[row * SSTRIDE + col] = make_float4(0.f, 0.f, 0.f, 0.f);
        }
        __syncthreads();   // covers coeff build + tile load

        // H-pass coefficients, broadcast-packed for f32x2
        u64 chp[13];
        #pragma unroll
        for (int j = 0; j < 13; ++j) chp[j] = pack2(sch[j], sch[j]);

        u64 accl[ROWS_PT], acch[ROWS_PT];
        #pragma unroll
        for (int o = 0; o < ROWS_PT; ++o) { accl[o] = 0ull; acch[o] = 0ull; }

        // H-pass: sliding window over 16 input rows -> 4 outputs x 13 taps.
        #pragma unroll
        for (int jr = 0; jr < ROWS_PT + 12; ++jr) {   // 16 rows
            float4 v = s[(rbase + jr) * SSTRIDE + 2 + wq];
            u64 vl = pack2(v.x, v.y);
            u64 vh = pack2(v.z, v.w);
            #pragma unroll
            for (int o = 0; o < ROWS_PT; ++o) {
                int j = jr - o;
                if (j >= 0 && j < 13) {
                    accl[o] = fma2(vl, chp[j], accl[o]);
                    acch[o] = fma2(vh, chp[j], acch[o]);
                }
            }
        }

        // W-pass coefficients, scalar (low register pressure)
        float cw[13];
        #pragma unroll
        for (int j = 0; j < 13; ++j) cw[j] = scw[j];

        // W-pass per row: 5 float4 loads cover the 20-float window.
        // f[i] = row float at global w-index 4*wq - 8 + i.
        // out.x (w=4wq) tap j: f[j+2]; y: f[j+3]; z: f[j+4]; w: f[j+5].
        #pragma unroll
        for (int o = 0; o < ROWS_PT; ++o) {
            const float4* r4 = &s[(rbase + o + RAD) * SSTRIDE];
            float f[20];
            #pragma unroll
            for (int m = 0; m < 5; ++m) {
                float4 v = r4[wq + m];
                f[4*m+0] = v.x; f[4*m+1] = v.y; f[4*m+2] = v.z; f[4*m+3] = v.w;
            }
            float4 res;
            unpack2(accl[o], res.x, res.y);
            unpack2(acch[o], res.z, res.w);
            #pragma unroll
            for (int j = 0; j < 13; ++j) {
                float cc = cw[j];
                res.x = fmaf(cc, f[2 + j], res.x);
                res.y = fmaf(cc, f[3 + j], res.y);
                res.z = fmaf(cc, f[4 + j], res.z);
                res.w = fmaf(cc, f[5 + j], res.w);
            }
            // Streaming store: output never re-read; keep L2 for halos.
            __stcs(&op[(hstart + rbase + o) * WF4 + wq], res);
        }
    } else {
        // ---------------- generic path (r >= 2), per-element ----------------
        const float* plane = x + (size_t)bc * (H_ * W_);
        float*       oplane = out + (size_t)bc * (H_ * W_);
        for (int o = 0; o < ROWS_PT; ++o) {
            int h = hstart + rbase + o;
            for (int c4 = 0; c4 < 4; ++c4) {
                int w = 4 * wq + c4;
                float res = plane[h * W_ + w];
                for (int k = 0; k < KTAP; ++k) {
                    float delta = (float)(k - KTAP/2) * rv;
                    float d0f   = floorf(delta);
                    float fr    = delta - d0f;
                    int   d0    = (int)d0f;

                    int h0 = h + d0, h1 = h0 + 1;
                    float s0 = (h0 >= 0 && h0 < H_) ? plane[h0 * W_ + w] : 0.f;
                    float s1 = (h1 >= 0 && h1 < H_) ? plane[h1 * W_ + w] : 0.f;
                    res += ((1.f - fr) * s0 + fr * s1) * wh[ch * KTAP + k];

                    int w0 = w + d0, w1 = w0 + 1;
                    float t0 = (w0 >= 0 && w0 < W_) ? plane[h * W_ + w0] : 0.f;
                    float t1 = (w1 >= 0 && w1 < W_) ? plane[h * W_ + w1] : 0.f;
                    res += ((1.f - fr) * t0 + fr * t1) * ww[ch * KTAP + k];
                }
                oplane[h * W_ + w] = res;
            }
        }
    }
}

extern "C" void kernel_launch(void* const* d_in, const int* in_sizes, int n_in,
                              void* d_out, int out_size)
{
    const float* x  = (const float*)d_in[0];
    const float* wh = (const float*)d_in[1];   // (C,1,7,1) -> C x 7 contiguous
    const float* ww = (const float*)d_in[2];   // (C,1,1,7) -> C x 7 contiguous
    const float* r  = (const float*)d_in[3];
    float* out = (float*)d_out;

    dim3 grid(H_ / TILE_H, B_ * C_);
    deform_axial_kernel<<<grid, NTHREADS>>>(x, wh, ww, r, out);
}